// round 14
// baseline (speedup 1.0000x reference)
#include <cuda_runtime.h>
#include <cuda_bf16.h>
#include <cuda_fp16.h>
#include <mma.h>
#include <math.h>
#include <stdint.h>

using namespace nvcuda;

#define N_NODES 100000
#define N_EDGES 1600000
#define NPAD    100096            // 782 * 128
#define DIM 128
#define OUT_DIM 47
#define SMA 136                   // smem leading dim (bf16 elems)
#define STG 132                   // fp32 staging leading dim (64-row stage)
#define TILE_ELT (128 * SMA)      // bf16 elems per tile (34816 B)
#define CSR_GRID ((N_EDGES / 4 + 255) / 256)   // 1563
#define WCONV_GRID 320

// ---------------- scratch ----------------
__device__ __half d_Gh[(size_t)NPAD * DIM];     // gather matrix (fp16)
__device__ float d_Z[(size_t)NPAD * DIM];       // self term (fp32)
__device__ __nv_bfloat16 d_A[(size_t)NPAD * DIM];  // activations (bf16)
__device__ __nv_bfloat16 d_Bh[5 * 128 * 128];   // weight tiles [n][k] bf16
__device__ float d_invd[N_NODES];
__device__ int   d_count[N_NODES];              // zero at load; scan re-zeroes each call
__device__ int   d_off[N_NODES + 1];
__device__ int   d_cursor[N_NODES];
__device__ int   d_esrc[N_EDGES];

// ---------------- fused prep: edge count (4/thread) + weight conversion ----------
__global__ void prep_kernel(const int* __restrict__ dst,
                            const float* __restrict__ Wl0, const float* __restrict__ Wr0,
                            const float* __restrict__ Wl1, const float* __restrict__ Wr1,
                            const float* __restrict__ Wl2, const float* __restrict__ Wr2,
                            __nv_bfloat16* __restrict__ bh) {
    if (blockIdx.x < CSR_GRID) {
        int t = blockIdx.x * blockDim.x + threadIdx.x;
        if (t * 4 < N_EDGES) {
            int4 d = __ldg(&((const int4*)dst)[t]);
            atomicAdd(&d_count[d.x], 1);
            atomicAdd(&d_count[d.y], 1);
            atomicAdd(&d_count[d.z], 1);
            atomicAdd(&d_count[d.w], 1);
        }
    } else {
        int i = (blockIdx.x - CSR_GRID) * blockDim.x + threadIdx.x;
        if (i >= 5 * 16384) return;
        int t = i >> 14, r = (i >> 7) & 127, k = i & 127;
        float v = 0.0f;
        if (t == 0) v = Wl0[(size_t)k * 128 + r];
        else if (t == 1) v = Wr0[(size_t)k * 128 + r];
        else if (t == 2) v = Wl1[(size_t)k * 128 + r];
        else if (t == 3) v = Wr1[(size_t)k * 128 + r];
        else {
            if (r < 64) { if (r < OUT_DIM) v = Wl2[(size_t)k * OUT_DIM + r]; }
            else        { if (r - 64 < OUT_DIM) v = Wr2[(size_t)k * OUT_DIM + (r - 64)]; }
        }
        bh[i] = __float2bfloat16_rn(v);
    }
}

__global__ void scan_kernel() {
    __shared__ int ssum[1024];
    const int t = threadIdx.x;
    const int CH = (N_NODES + 1023) / 1024;
    int lo = t * CH;
    int hi = lo + CH; if (hi > N_NODES) hi = N_NODES;
    if (lo > N_NODES) lo = N_NODES;
    int s = 0;
    for (int i = lo; i < hi; i++) s += d_count[i];
    ssum[t] = s;
    __syncthreads();
    for (int o = 1; o < 1024; o <<= 1) {
        int v = (t >= o) ? ssum[t - o] : 0;
        __syncthreads();
        ssum[t] += v;
        __syncthreads();
    }
    int run = (t > 0) ? ssum[t - 1] : 0;
    for (int i = lo; i < hi; i++) {
        int ci = d_count[i];
        d_count[i] = 0;                  // re-zero for next graph replay
        d_off[i] = run;
        d_cursor[i] = run;
        d_invd[i] = (ci > 0) ? (1.0f / (float)ci) : 0.0f;
        run += ci;
    }
    if (t == 1023) d_off[N_NODES] = ssum[1023];
}

__global__ void scatter_kernel(const int* __restrict__ src, const int* __restrict__ dst) {
    int t = blockIdx.x * blockDim.x + threadIdx.x;
    if (t * 4 >= N_EDGES) return;
    int4 d = __ldg(&((const int4*)dst)[t]);
    int4 s = __ldg(&((const int4*)src)[t]);
    d_esrc[atomicAdd(&d_cursor[d.x], 1)] = s.x;
    d_esrc[atomicAdd(&d_cursor[d.y], 1)] = s.y;
    d_esrc[atomicAdd(&d_cursor[d.z], 1)] = s.z;
    d_esrc[atomicAdd(&d_cursor[d.w], 1)] = s.w;
}

// ---------------- WMMA GEMM (single bf16 product), 256 threads, acc[2][4] ----------
// smem: sA[0], B_p at (1+p)*TILE_ELT. Phase-0 epilogue reuses B0's area as a
// 64-row fp32 stage -> smem 104.4 KB -> 2 CTAs/SM.
#define GEMM_SMEM_MAX ((1 + 2) * TILE_ELT * 2)

__global__ __launch_bounds__(256, 2)
void gemm_wmma(const float* __restrict__ X, const __nv_bfloat16* __restrict__ A,
               const __nv_bfloat16* __restrict__ Bh,
               int nphase, __half* __restrict__ Gh, float* __restrict__ Z, int M) {
    extern __shared__ __nv_bfloat16 sm[];
    __nv_bfloat16* sA = sm;
    const int tid = threadIdx.x;
    const int m0 = blockIdx.x * 128;

    if (X) {
#pragma unroll
        for (int i = 0; i < 16; i++) {
            int u = i * 256 + tid;
            int row = u >> 5, c4 = (u & 31) * 4;
            float4 v = make_float4(0.f, 0.f, 0.f, 0.f);
            if (m0 + row < M)
                v = *(const float4*)(X + (size_t)(m0 + row) * 128 + c4);
            __nv_bfloat16 h[4];
            h[0] = __float2bfloat16_rn(v.x);
            h[1] = __float2bfloat16_rn(v.y);
            h[2] = __float2bfloat16_rn(v.z);
            h[3] = __float2bfloat16_rn(v.w);
            *(uint2*)(sA + row * SMA + c4) = *(uint2*)h;
        }
    } else {
#pragma unroll
        for (int i = 0; i < 8; i++) {
            int u = i * 256 + tid;
            int row = u >> 4, c8 = (u & 15) * 8;
            uint4 va = make_uint4(0u, 0u, 0u, 0u);
            if (m0 + row < M)
                va = *(const uint4*)(A + (size_t)(m0 + row) * 128 + c8);
            *(uint4*)(sA + row * SMA + c8) = va;
        }
    }
    for (int p = 0; p < nphase; p++) {
        __nv_bfloat16* dB = sm + (1 + p) * TILE_ELT;
        const __nv_bfloat16* gB = Bh + (size_t)p * 16384;
#pragma unroll
        for (int i = 0; i < 8; i++) {
            int u = i * 256 + tid;
            int row = u >> 4, c8 = (u & 15) * 8;
            *(uint4*)(dB + row * SMA + c8) = *(const uint4*)(gB + row * 128 + c8);
        }
    }
    __syncthreads();

    const int wid = tid >> 5;
    const int wm = (wid & 3) * 32;
    const int wn = (wid >> 2) * 64;

    for (int p = 0; p < nphase; p++) {
        const __nv_bfloat16* sB = sm + (1 + p) * TILE_ELT;

        wmma::fragment<wmma::accumulator, 16, 16, 16, float> acc[2][4];
#pragma unroll
        for (int i = 0; i < 2; i++)
#pragma unroll
            for (int j = 0; j < 4; j++) wmma::fill_fragment(acc[i][j], 0.0f);

#pragma unroll
        for (int ks = 0; ks < 8; ks++) {
            wmma::fragment<wmma::matrix_a, 16, 16, 16, __nv_bfloat16, wmma::row_major> fa[2];
            wmma::fragment<wmma::matrix_b, 16, 16, 16, __nv_bfloat16, wmma::col_major> fb[4];
#pragma unroll
            for (int i = 0; i < 2; i++)
                wmma::load_matrix_sync(fa[i], sA + (wm + i * 16) * SMA + ks * 16, SMA);
#pragma unroll
            for (int j = 0; j < 4; j++)
                wmma::load_matrix_sync(fb[j], sB + (wn + j * 16) * SMA + ks * 16, SMA);
#pragma unroll
            for (int i = 0; i < 2; i++)
#pragma unroll
                for (int j = 0; j < 4; j++)
                    wmma::mma_sync(acc[i][j], fa[i], fb[j], acc[i][j]);
        }

        if (p == 0) {
            float* stage = (float*)(sm + TILE_ELT);
            for (int hf = 0; hf < 2; hf++) {
                __syncthreads();
                if ((wm >> 6) == hf) {
                    int wmr = wm & 63;
#pragma unroll
                    for (int i = 0; i < 2; i++)
#pragma unroll
                        for (int j = 0; j < 4; j++)
                            wmma::store_matrix_sync(stage + (wmr + i * 16) * STG + wn + j * 16,
                                                    acc[i][j], STG, wmma::mem_row_major);
                }
                __syncthreads();

                if (nphase == 2) {
                    for (int t = tid; t < 64 * 16; t += 256) {
                        int r = t >> 4, c8 = (t & 15) * 8;
                        int g = m0 + hf * 64 + r;
                        if (g < M) {
                            __half h8[8];
#pragma unroll
                            for (int j = 0; j < 8; j++)
                                h8[j] = __float2half_rn(stage[r * STG + c8 + j]);
                            *(uint4*)(Gh + (size_t)g * 128 + c8) = *(uint4*)h8;
                        }
                    }
                } else {
                    for (int t = tid; t < 64 * 8; t += 256) {
                        int r = t >> 3, c8 = (t & 7) * 8;
                        int g = m0 + hf * 64 + r;
                        if (g < M) {
                            __half h8[8];
#pragma unroll
                            for (int j = 0; j < 8; j++)
                                h8[j] = __float2half_rn(stage[r * STG + c8 + j]);
                            *(uint4*)(Gh + (size_t)g * 64 + c8) = *(uint4*)h8;
                        }
                    }
                    for (int t = tid; t < 64 * 16; t += 256) {
                        int r = t >> 4, c4 = (t & 15) * 4;
                        int g = m0 + hf * 64 + r;
                        if (g < M)
                            *(float4*)(Z + (size_t)g * 64 + c4) =
                                *(float4*)(stage + r * STG + 64 + c4);
                    }
                }
            }
        } else {
#pragma unroll
            for (int i = 0; i < 2; i++)
#pragma unroll
                for (int j = 0; j < 4; j++)
                    wmma::store_matrix_sync(Z + (size_t)(m0 + wm + i * 16) * 128 + wn + j * 16,
                                            acc[i][j], 128, wmma::mem_row_major);
        }
    }
}

// ---------------- aggregation, warp per node (fp16 gather, 8-edge unroll) ----------
__device__ __forceinline__ void acc_row(float* a, uint2 u) {
    float2 p0 = __half22float2(*(const __half2*)&u.x);
    float2 p1 = __half22float2(*(const __half2*)&u.y);
    a[0] += p0.x; a[1] += p0.y; a[2] += p1.x; a[3] += p1.y;
}

__global__ void agg128_warp(const __half* __restrict__ G, const float* __restrict__ Z,
                            const float* __restrict__ bias,
                            __nv_bfloat16* __restrict__ oA) {
    int w = (blockIdx.x * blockDim.x + threadIdx.x) >> 5;
    int lane = threadIdx.x & 31;
    if (w >= N_NODES) return;
    const int e0 = d_off[w], e1 = d_off[w + 1];
    const uint2* Gv = (const uint2*)G;
    float a0[4] = {0.f, 0.f, 0.f, 0.f};
    float a1[4] = {0.f, 0.f, 0.f, 0.f};
    float a2[4] = {0.f, 0.f, 0.f, 0.f};
    float a3[4] = {0.f, 0.f, 0.f, 0.f};
    int i = e0;
    for (; i + 8 <= e1; i += 8) {
        int s0 = __ldg(&d_esrc[i]);
        int s1 = __ldg(&d_esrc[i + 1]);
        int s2 = __ldg(&d_esrc[i + 2]);
        int s3 = __ldg(&d_esrc[i + 3]);
        int s4 = __ldg(&d_esrc[i + 4]);
        int s5 = __ldg(&d_esrc[i + 5]);
        int s6 = __ldg(&d_esrc[i + 6]);
        int s7 = __ldg(&d_esrc[i + 7]);
        uint2 u0 = __ldg(&Gv[(size_t)s0 * 32 + lane]);
        uint2 u1 = __ldg(&Gv[(size_t)s1 * 32 + lane]);
        uint2 u2 = __ldg(&Gv[(size_t)s2 * 32 + lane]);
        uint2 u3 = __ldg(&Gv[(size_t)s3 * 32 + lane]);
        uint2 u4 = __ldg(&Gv[(size_t)s4 * 32 + lane]);
        uint2 u5 = __ldg(&Gv[(size_t)s5 * 32 + lane]);
        uint2 u6 = __ldg(&Gv[(size_t)s6 * 32 + lane]);
        uint2 u7 = __ldg(&Gv[(size_t)s7 * 32 + lane]);
        acc_row(a0, u0); acc_row(a1, u1); acc_row(a2, u2); acc_row(a3, u3);
        acc_row(a0, u4); acc_row(a1, u5); acc_row(a2, u6); acc_row(a3, u7);
    }
    for (; i + 2 <= e1; i += 2) {
        int s0 = __ldg(&d_esrc[i]);
        int s1 = __ldg(&d_esrc[i + 1]);
        uint2 u0 = __ldg(&Gv[(size_t)s0 * 32 + lane]);
        uint2 u1 = __ldg(&Gv[(size_t)s1 * 32 + lane]);
        acc_row(a0, u0); acc_row(a1, u1);
    }
    if (i < e1)
        acc_row(a0, __ldg(&Gv[(size_t)__ldg(&d_esrc[i]) * 32 + lane]));

    float inv = d_invd[w];
    float4 z = __ldg(&((const float4*)Z)[(size_t)w * 32 + lane]);
    float4 b = __ldg(&((const float4*)bias)[lane]);
    float o[4];
    o[0] = fmaxf(z.x + b.x + inv * ((a0[0] + a1[0]) + (a2[0] + a3[0])), 0.f);
    o[1] = fmaxf(z.y + b.y + inv * ((a0[1] + a1[1]) + (a2[1] + a3[1])), 0.f);
    o[2] = fmaxf(z.z + b.z + inv * ((a0[2] + a1[2]) + (a2[2] + a3[2])), 0.f);
    o[3] = fmaxf(z.w + b.w + inv * ((a0[3] + a1[3]) + (a2[3] + a3[3])), 0.f);

    __nv_bfloat16 hb[4];
#pragma unroll
    for (int j = 0; j < 4; j++) hb[j] = __float2bfloat16_rn(o[j]);
    *(uint2*)&oA[(size_t)w * 128 + lane * 4] = *(uint2*)hb;
}

// ---------------- layer-2 agg + log_softmax (half-warp per edge) ----------------
__global__ void agg_lsm47_warp(const __half* __restrict__ G, const float* __restrict__ Z,
                               const float* __restrict__ bias, float* __restrict__ out) {
    int v = (blockIdx.x * blockDim.x + threadIdx.x) >> 5;
    int lane = threadIdx.x & 31;
    if (v >= N_NODES) return;
    const int e0 = d_off[v], e1 = d_off[v + 1];
    const int half = lane >> 4;
    const int sub = lane & 15;
    const uint2* Gv = (const uint2*)G;

    float a[4] = {0.f, 0.f, 0.f, 0.f};
    int i = e0 + half;
    for (; i + 2 < e1; i += 4) {
        int s0 = __ldg(&d_esrc[i]);
        int s1 = __ldg(&d_esrc[i + 2]);
        uint2 u0 = __ldg(&Gv[(size_t)s0 * 16 + sub]);
        uint2 u1 = __ldg(&Gv[(size_t)s1 * 16 + sub]);
        acc_row(a, u0); acc_row(a, u1);
    }
    if (i < e1)
        acc_row(a, __ldg(&Gv[(size_t)__ldg(&d_esrc[i]) * 16 + sub]));
#pragma unroll
    for (int j = 0; j < 4; j++) a[j] += __shfl_xor_sync(0xFFFFFFFFu, a[j], 16);

    float inv = d_invd[v];
    float4 z = __ldg(&((const float4*)(Z + (size_t)v * 64))[sub]);
    float zz[4] = {z.x, z.y, z.z, z.w};
    float vals[4];
    float m = -INFINITY;
#pragma unroll
    for (int j = 0; j < 4; j++) {
        int c = 4 * sub + j;
        vals[j] = (c < OUT_DIM) ? (zz[j] + __ldg(&bias[c]) + inv * a[j]) : -INFINITY;
        m = fmaxf(m, vals[j]);
    }
#pragma unroll
    for (int o = 16; o > 0; o >>= 1) m = fmaxf(m, __shfl_xor_sync(0xFFFFFFFFu, m, o));
    float s = 0.f;
    if (half == 0) {
#pragma unroll
        for (int j = 0; j < 4; j++) {
            int c = 4 * sub + j;
            if (c < OUT_DIM) s += expf(vals[j] - m);
        }
    }
#pragma unroll
    for (int o = 16; o > 0; o >>= 1) s += __shfl_xor_sync(0xFFFFFFFFu, s, o);
    float l = m + logf(s);

    if (half == 0) {
        float* orow = out + (size_t)v * OUT_DIM;
#pragma unroll
        for (int j = 0; j < 4; j++) {
            int c = 4 * sub + j;
            if (c < OUT_DIM) orow[c] = vals[j] - l;
        }
    }
}

// ---------------- launch ----------------
extern "C" void kernel_launch(void* const* d_in, const int* in_sizes, int n_in,
                              void* d_out, int out_size) {
    const float* x   = (const float*)d_in[0];
    const int*   src = (const int*)d_in[1];
    const int*   dst = (const int*)d_in[2];
    const float* Wl0 = (const float*)d_in[3];
    const float* bl0 = (const float*)d_in[4];
    const float* Wr0 = (const float*)d_in[5];
    const float* Wl1 = (const float*)d_in[6];
    const float* bl1 = (const float*)d_in[7];
    const float* Wr1 = (const float*)d_in[8];
    const float* Wl2 = (const float*)d_in[9];
    const float* bl2 = (const float*)d_in[10];
    const float* Wr2 = (const float*)d_in[11];
    float* out = (float*)d_out;

    void *pGh, *pZ, *pA, *pBh;
    cudaGetSymbolAddress(&pGh, d_Gh);
    cudaGetSymbolAddress(&pZ, d_Z);
    cudaGetSymbolAddress(&pA, d_A);
    cudaGetSymbolAddress(&pBh, d_Bh);
    __half* Gh = (__half*)pGh;
    float* Z = (float*)pZ;
    __nv_bfloat16* A = (__nv_bfloat16*)pA;
    __nv_bfloat16* Bh = (__nv_bfloat16*)pBh;

    cudaFuncSetAttribute(gemm_wmma, cudaFuncAttributeMaxDynamicSharedMemorySize,
                         GEMM_SMEM_MAX);

    const int gemm_grid = NPAD / 128;
    const int aggw_grid = (N_NODES * 32 + 255) / 256;
    const size_t smem2 = (size_t)(1 + 2) * TILE_ELT * 2;   // 104448 B -> 2 CTAs/SM
    const size_t smem1 = (size_t)(1 + 1) * TILE_ELT * 2;   // 69632 B  -> 3 CTAs/SM

    // Order: prep(1) scan(2) scatter(3) gemm0(4) agg128(5)<-ncu capture ...
    // d_count is zeroed at module load and re-zeroed by scan each call.
    prep_kernel<<<CSR_GRID + WCONV_GRID, 256>>>(dst, Wl0, Wr0, Wl1, Wr1, Wl2, Wr2, Bh);
    scan_kernel<<<1, 1024>>>();
    scatter_kernel<<<CSR_GRID, 256>>>(src, dst);

    // Layer 0
    gemm_wmma<<<gemm_grid, 256, smem2>>>(x, nullptr, Bh, 2, Gh, Z, N_NODES);
    agg128_warp<<<aggw_grid, 256>>>(Gh, Z, bl0, A);

    // Layer 1
    gemm_wmma<<<gemm_grid, 256, smem2>>>(nullptr, A, Bh + 2 * 16384, 2, Gh, Z, N_NODES);
    agg128_warp<<<aggw_grid, 256>>>(Gh, Z, bl1, A);

    // Layer 2
    gemm_wmma<<<gemm_grid, 256, smem1>>>(nullptr, A, Bh + 4 * 16384, 1, Gh, Z, N_NODES);
    agg_lsm47_warp<<<aggw_grid, 256>>>(Gh, Z, bl2, out);
}

// round 15
// speedup vs baseline: 1.1347x; 1.1347x over previous
#include <cuda_runtime.h>
#include <cuda_bf16.h>
#include <cuda_fp16.h>
#include <mma.h>
#include <math.h>
#include <stdint.h>

using namespace nvcuda;

#define N_NODES 100000
#define N_EDGES 1600000
#define NPAD    100096            // 782 * 128
#define DIM 128
#define OUT_DIM 47
#define SMA 136                   // smem leading dim (bf16 elems)
#define STG 132                   // fp32 staging leading dim (64-row stage)
#define TILE_ELT (128 * SMA)      // bf16 elems per tile (34816 B)

// ---------------- scratch ----------------
__device__ __half d_Gh[(size_t)NPAD * DIM];     // gather matrix (fp16)
__device__ __half d_Zh[(size_t)NPAD * DIM];     // self term (fp16)
__device__ __nv_bfloat16 d_A[(size_t)NPAD * DIM];  // activations (bf16)
__device__ __nv_bfloat16 d_Bh[5 * 128 * 128];   // weight tiles [n][k] bf16
__device__ float d_invd[N_NODES];
__device__ int   d_count[N_NODES];
__device__ int   d_off[N_NODES + 1];
__device__ int   d_cursor[N_NODES];
__device__ int   d_esrc[N_EDGES];

// ---------------- CSR build (vectorized: 4 edges/thread) ----------------
__global__ void count_kernel(const int* __restrict__ dst) {
    int t = blockIdx.x * blockDim.x + threadIdx.x;
    if (t * 4 >= N_EDGES) return;
    int4 d = __ldg(&((const int4*)dst)[t]);
    atomicAdd(&d_count[d.x], 1);
    atomicAdd(&d_count[d.y], 1);
    atomicAdd(&d_count[d.z], 1);
    atomicAdd(&d_count[d.w], 1);
}

__global__ void scan_kernel() {
    __shared__ int ssum[1024];
    const int t = threadIdx.x;
    const int CH = (N_NODES + 1023) / 1024;
    int lo = t * CH;
    int hi = lo + CH; if (hi > N_NODES) hi = N_NODES;
    if (lo > N_NODES) lo = N_NODES;
    int s = 0;
    for (int i = lo; i < hi; i++) s += d_count[i];
    ssum[t] = s;
    __syncthreads();
    for (int o = 1; o < 1024; o <<= 1) {
        int v = (t >= o) ? ssum[t - o] : 0;
        __syncthreads();
        ssum[t] += v;
        __syncthreads();
    }
    int run = (t > 0) ? ssum[t - 1] : 0;
    for (int i = lo; i < hi; i++) {
        int ci = d_count[i];
        d_off[i] = run;
        d_cursor[i] = run;
        d_invd[i] = (ci > 0) ? (1.0f / (float)ci) : 0.0f;
        run += ci;
    }
    if (t == 1023) d_off[N_NODES] = ssum[1023];
}

__global__ void scatter_kernel(const int* __restrict__ src, const int* __restrict__ dst) {
    int t = blockIdx.x * blockDim.x + threadIdx.x;
    if (t * 4 >= N_EDGES) return;
    int4 d = __ldg(&((const int4*)dst)[t]);
    int4 s = __ldg(&((const int4*)src)[t]);
    d_esrc[atomicAdd(&d_cursor[d.x], 1)] = s.x;
    d_esrc[atomicAdd(&d_cursor[d.y], 1)] = s.y;
    d_esrc[atomicAdd(&d_cursor[d.z], 1)] = s.z;
    d_esrc[atomicAdd(&d_cursor[d.w], 1)] = s.w;
}

// ---------------- weight conversion (bf16, single-rounded), one launch ------------
__global__ void wconv_all(const float* __restrict__ Wl0, const float* __restrict__ Wr0,
                          const float* __restrict__ Wl1, const float* __restrict__ Wr1,
                          const float* __restrict__ Wl2, const float* __restrict__ Wr2,
                          __nv_bfloat16* __restrict__ bh) {
    int i = blockIdx.x * blockDim.x + threadIdx.x;
    if (i >= 5 * 16384) return;
    int t = i >> 14, r = (i >> 7) & 127, k = i & 127;
    float v = 0.0f;
    if (t == 0) v = Wl0[(size_t)k * 128 + r];
    else if (t == 1) v = Wr0[(size_t)k * 128 + r];
    else if (t == 2) v = Wl1[(size_t)k * 128 + r];
    else if (t == 3) v = Wr1[(size_t)k * 128 + r];
    else {
        if (r < 64) { if (r < OUT_DIM) v = Wl2[(size_t)k * OUT_DIM + r]; }
        else        { if (r - 64 < OUT_DIM) v = Wr2[(size_t)k * OUT_DIM + (r - 64)]; }
    }
    bh[i] = __float2bfloat16_rn(v);
}

// ---------------- WMMA GEMM (single bf16 product), 256 threads, acc[2][4] ----------
// smem: sA[0], B_p at (1+p)*TILE_ELT. Phase-p epilogue reuses B_p's area as a
// 64-row fp32 stage (B_p dead after phase-p mainloop) -> smem 104.4 KB -> 2 CTAs/SM.
// Phase 0 -> Gh fp16; phase 1 -> Zh fp16. nphase==1: cols 0-63 -> Gh, 64-127 -> Zh.
#define GEMM_SMEM_MAX ((1 + 2) * TILE_ELT * 2)

__global__ __launch_bounds__(256, 2)
void gemm_wmma(const float* __restrict__ X, const __nv_bfloat16* __restrict__ A,
               const __nv_bfloat16* __restrict__ Bh,
               int nphase, __half* __restrict__ Gh, __half* __restrict__ Zh, int M) {
    extern __shared__ __nv_bfloat16 sm[];
    __nv_bfloat16* sA = sm;
    const int tid = threadIdx.x;
    const int m0 = blockIdx.x * 128;

    if (X) {
#pragma unroll
        for (int i = 0; i < 16; i++) {
            int u = i * 256 + tid;
            int row = u >> 5, c4 = (u & 31) * 4;
            float4 v = make_float4(0.f, 0.f, 0.f, 0.f);
            if (m0 + row < M)
                v = *(const float4*)(X + (size_t)(m0 + row) * 128 + c4);
            __nv_bfloat16 h[4];
            h[0] = __float2bfloat16_rn(v.x);
            h[1] = __float2bfloat16_rn(v.y);
            h[2] = __float2bfloat16_rn(v.z);
            h[3] = __float2bfloat16_rn(v.w);
            *(uint2*)(sA + row * SMA + c4) = *(uint2*)h;
        }
    } else {
#pragma unroll
        for (int i = 0; i < 8; i++) {
            int u = i * 256 + tid;
            int row = u >> 4, c8 = (u & 15) * 8;
            uint4 va = make_uint4(0u, 0u, 0u, 0u);
            if (m0 + row < M)
                va = *(const uint4*)(A + (size_t)(m0 + row) * 128 + c8);
            *(uint4*)(sA + row * SMA + c8) = va;
        }
    }
    for (int p = 0; p < nphase; p++) {
        __nv_bfloat16* dB = sm + (1 + p) * TILE_ELT;
        const __nv_bfloat16* gB = Bh + (size_t)p * 16384;
#pragma unroll
        for (int i = 0; i < 8; i++) {
            int u = i * 256 + tid;
            int row = u >> 4, c8 = (u & 15) * 8;
            *(uint4*)(dB + row * SMA + c8) = *(const uint4*)(gB + row * 128 + c8);
        }
    }
    __syncthreads();

    const int wid = tid >> 5;
    const int wm = (wid & 3) * 32;
    const int wn = (wid >> 2) * 64;

    for (int p = 0; p < nphase; p++) {
        const __nv_bfloat16* sB = sm + (1 + p) * TILE_ELT;

        wmma::fragment<wmma::accumulator, 16, 16, 16, float> acc[2][4];
#pragma unroll
        for (int i = 0; i < 2; i++)
#pragma unroll
            for (int j = 0; j < 4; j++) wmma::fill_fragment(acc[i][j], 0.0f);

#pragma unroll
        for (int ks = 0; ks < 8; ks++) {
            wmma::fragment<wmma::matrix_a, 16, 16, 16, __nv_bfloat16, wmma::row_major> fa[2];
            wmma::fragment<wmma::matrix_b, 16, 16, 16, __nv_bfloat16, wmma::col_major> fb[4];
#pragma unroll
            for (int i = 0; i < 2; i++)
                wmma::load_matrix_sync(fa[i], sA + (wm + i * 16) * SMA + ks * 16, SMA);
#pragma unroll
            for (int j = 0; j < 4; j++)
                wmma::load_matrix_sync(fb[j], sB + (wn + j * 16) * SMA + ks * 16, SMA);
#pragma unroll
            for (int i = 0; i < 2; i++)
#pragma unroll
                for (int j = 0; j < 4; j++)
                    wmma::mma_sync(acc[i][j], fa[i], fb[j], acc[i][j]);
        }

        // staged epilogue in B_p's smem area (B_p dead after this phase's mainloop)
        float* stage = (float*)(sm + (1 + p) * TILE_ELT);
        for (int hf = 0; hf < 2; hf++) {
            __syncthreads();
            if ((wm >> 6) == hf) {
                int wmr = wm & 63;
#pragma unroll
                for (int i = 0; i < 2; i++)
#pragma unroll
                    for (int j = 0; j < 4; j++)
                        wmma::store_matrix_sync(stage + (wmr + i * 16) * STG + wn + j * 16,
                                                acc[i][j], STG, wmma::mem_row_major);
            }
            __syncthreads();

            if (nphase == 2) {
                __half* dstp = (p == 0) ? Gh : Zh;
                for (int t = tid; t < 64 * 16; t += 256) {
                    int r = t >> 4, c8 = (t & 15) * 8;
                    int g = m0 + hf * 64 + r;
                    if (g < M) {
                        __half h8[8];
#pragma unroll
                        for (int j = 0; j < 8; j++)
                            h8[j] = __float2half_rn(stage[r * STG + c8 + j]);
                        *(uint4*)(dstp + (size_t)g * 128 + c8) = *(uint4*)h8;
                    }
                }
            } else {
                // cols 0-63 -> Gh stride 64; cols 64-127 -> Zh stride 64
                for (int t = tid; t < 64 * 16; t += 256) {
                    int r = t >> 3, c8 = ((t & 7)) * 8;     // 8 col-groups per row half
                    int half = (t >> 3) & 1;                 // unused placeholder
                    (void)half;
                    r = t >> 4;
                    int cg = t & 15;                         // 0..15: col group of 8
                    int g = m0 + hf * 64 + r;
                    if (g < M) {
                        __half h8[8];
                        int c0 = cg * 8;
#pragma unroll
                        for (int j = 0; j < 8; j++)
                            h8[j] = __float2half_rn(stage[r * STG + c0 + j]);
                        if (cg < 8)
                            *(uint4*)(Gh + (size_t)g * 64 + c0) = *(uint4*)h8;
                        else
                            *(uint4*)(Zh + (size_t)g * 64 + (c0 - 64)) = *(uint4*)h8;
                    }
                    (void)c8;
                }
            }
        }
    }
}

// ---------------- aggregation, warp per node (fp16 gather, 8-edge unroll) ----------
__device__ __forceinline__ void acc_row(float* a, uint2 u) {
    float2 p0 = __half22float2(*(const __half2*)&u.x);
    float2 p1 = __half22float2(*(const __half2*)&u.y);
    a[0] += p0.x; a[1] += p0.y; a[2] += p1.x; a[3] += p1.y;
}

__global__ void agg128_warp(const __half* __restrict__ G, const __half* __restrict__ Zh,
                            const float* __restrict__ bias,
                            __nv_bfloat16* __restrict__ oA) {
    int w = (blockIdx.x * blockDim.x + threadIdx.x) >> 5;
    int lane = threadIdx.x & 31;
    if (w >= N_NODES) return;
    const int e0 = d_off[w], e1 = d_off[w + 1];
    const uint2* Gv = (const uint2*)G;
    float a0[4] = {0.f, 0.f, 0.f, 0.f};
    float a1[4] = {0.f, 0.f, 0.f, 0.f};
    float a2[4] = {0.f, 0.f, 0.f, 0.f};
    float a3[4] = {0.f, 0.f, 0.f, 0.f};
    int i = e0;
    for (; i + 8 <= e1; i += 8) {
        int s0 = __ldg(&d_esrc[i]);
        int s1 = __ldg(&d_esrc[i + 1]);
        int s2 = __ldg(&d_esrc[i + 2]);
        int s3 = __ldg(&d_esrc[i + 3]);
        int s4 = __ldg(&d_esrc[i + 4]);
        int s5 = __ldg(&d_esrc[i + 5]);
        int s6 = __ldg(&d_esrc[i + 6]);
        int s7 = __ldg(&d_esrc[i + 7]);
        uint2 u0 = __ldg(&Gv[(size_t)s0 * 32 + lane]);
        uint2 u1 = __ldg(&Gv[(size_t)s1 * 32 + lane]);
        uint2 u2 = __ldg(&Gv[(size_t)s2 * 32 + lane]);
        uint2 u3 = __ldg(&Gv[(size_t)s3 * 32 + lane]);
        uint2 u4 = __ldg(&Gv[(size_t)s4 * 32 + lane]);
        uint2 u5 = __ldg(&Gv[(size_t)s5 * 32 + lane]);
        uint2 u6 = __ldg(&Gv[(size_t)s6 * 32 + lane]);
        uint2 u7 = __ldg(&Gv[(size_t)s7 * 32 + lane]);
        acc_row(a0, u0); acc_row(a1, u1); acc_row(a2, u2); acc_row(a3, u3);
        acc_row(a0, u4); acc_row(a1, u5); acc_row(a2, u6); acc_row(a3, u7);
    }
    for (; i + 2 <= e1; i += 2) {
        int s0 = __ldg(&d_esrc[i]);
        int s1 = __ldg(&d_esrc[i + 1]);
        uint2 u0 = __ldg(&Gv[(size_t)s0 * 32 + lane]);
        uint2 u1 = __ldg(&Gv[(size_t)s1 * 32 + lane]);
        acc_row(a0, u0); acc_row(a1, u1);
    }
    if (i < e1)
        acc_row(a0, __ldg(&Gv[(size_t)__ldg(&d_esrc[i]) * 32 + lane]));

    float inv = d_invd[w];
    uint2 zu = __ldg(&((const uint2*)Zh)[(size_t)w * 32 + lane]);
    float zz[4];
    {
        float2 pz0 = __half22float2(*(const __half2*)&zu.x);
        float2 pz1 = __half22float2(*(const __half2*)&zu.y);
        zz[0] = pz0.x; zz[1] = pz0.y; zz[2] = pz1.x; zz[3] = pz1.y;
    }
    float4 b = __ldg(&((const float4*)bias)[lane]);
    float o[4];
    o[0] = fmaxf(zz[0] + b.x + inv * ((a0[0] + a1[0]) + (a2[0] + a3[0])), 0.f);
    o[1] = fmaxf(zz[1] + b.y + inv * ((a0[1] + a1[1]) + (a2[1] + a3[1])), 0.f);
    o[2] = fmaxf(zz[2] + b.z + inv * ((a0[2] + a1[2]) + (a2[2] + a3[2])), 0.f);
    o[3] = fmaxf(zz[3] + b.w + inv * ((a0[3] + a1[3]) + (a2[3] + a3[3])), 0.f);

    __nv_bfloat16 hb[4];
#pragma unroll
    for (int j = 0; j < 4; j++) hb[j] = __float2bfloat16_rn(o[j]);
    *(uint2*)&oA[(size_t)w * 128 + lane * 4] = *(uint2*)hb;
}

// ---------------- layer-2 agg + log_softmax (half-warp per edge) ----------------
__global__ void agg_lsm47_warp(const __half* __restrict__ G, const __half* __restrict__ Zh,
                               const float* __restrict__ bias, float* __restrict__ out) {
    int v = (blockIdx.x * blockDim.x + threadIdx.x) >> 5;
    int lane = threadIdx.x & 31;
    if (v >= N_NODES) return;
    const int e0 = d_off[v], e1 = d_off[v + 1];
    const int half = lane >> 4;
    const int sub = lane & 15;
    const uint2* Gv = (const uint2*)G;

    float a[4] = {0.f, 0.f, 0.f, 0.f};
    int i = e0 + half;
    for (; i + 2 < e1; i += 4) {
        int s0 = __ldg(&d_esrc[i]);
        int s1 = __ldg(&d_esrc[i + 2]);
        uint2 u0 = __ldg(&Gv[(size_t)s0 * 16 + sub]);
        uint2 u1 = __ldg(&Gv[(size_t)s1 * 16 + sub]);
        acc_row(a, u0); acc_row(a, u1);
    }
    if (i < e1)
        acc_row(a, __ldg(&Gv[(size_t)__ldg(&d_esrc[i]) * 16 + sub]));
#pragma unroll
    for (int j = 0; j < 4; j++) a[j] += __shfl_xor_sync(0xFFFFFFFFu, a[j], 16);

    float inv = d_invd[v];
    uint2 zu = __ldg(&((const uint2*)(Zh + (size_t)v * 64))[sub]);
    float zz[4];
    {
        float2 pz0 = __half22float2(*(const __half2*)&zu.x);
        float2 pz1 = __half22float2(*(const __half2*)&zu.y);
        zz[0] = pz0.x; zz[1] = pz0.y; zz[2] = pz1.x; zz[3] = pz1.y;
    }
    float vals[4];
    float m = -INFINITY;
#pragma unroll
    for (int j = 0; j < 4; j++) {
        int c = 4 * sub + j;
        vals[j] = (c < OUT_DIM) ? (zz[j] + __ldg(&bias[c]) + inv * a[j]) : -INFINITY;
        m = fmaxf(m, vals[j]);
    }
#pragma unroll
    for (int o = 16; o > 0; o >>= 1) m = fmaxf(m, __shfl_xor_sync(0xFFFFFFFFu, m, o));
    float s = 0.f;
    if (half == 0) {
#pragma unroll
        for (int j = 0; j < 4; j++) {
            int c = 4 * sub + j;
            if (c < OUT_DIM) s += expf(vals[j] - m);
        }
    }
#pragma unroll
    for (int o = 16; o > 0; o >>= 1) s += __shfl_xor_sync(0xFFFFFFFFu, s, o);
    float l = m + logf(s);

    if (half == 0) {
        float* orow = out + (size_t)v * OUT_DIM;
#pragma unroll
        for (int j = 0; j < 4; j++) {
            int c = 4 * sub + j;
            if (c < OUT_DIM) orow[c] = vals[j] - l;
        }
    }
}

// ---------------- launch ----------------
extern "C" void kernel_launch(void* const* d_in, const int* in_sizes, int n_in,
                              void* d_out, int out_size) {
    const float* x   = (const float*)d_in[0];
    const int*   src = (const int*)d_in[1];
    const int*   dst = (const int*)d_in[2];
    const float* Wl0 = (const float*)d_in[3];
    const float* bl0 = (const float*)d_in[4];
    const float* Wr0 = (const float*)d_in[5];
    const float* Wl1 = (const float*)d_in[6];
    const float* bl1 = (const float*)d_in[7];
    const float* Wr1 = (const float*)d_in[8];
    const float* Wl2 = (const float*)d_in[9];
    const float* bl2 = (const float*)d_in[10];
    const float* Wr2 = (const float*)d_in[11];
    float* out = (float*)d_out;

    void *pGh, *pZh, *pA, *pBh, *pCnt;
    cudaGetSymbolAddress(&pGh, d_Gh);
    cudaGetSymbolAddress(&pZh, d_Zh);
    cudaGetSymbolAddress(&pA, d_A);
    cudaGetSymbolAddress(&pBh, d_Bh);
    cudaGetSymbolAddress(&pCnt, d_count);
    __half* Gh = (__half*)pGh;
    __half* Zh = (__half*)pZh;
    __nv_bfloat16* A = (__nv_bfloat16*)pA;
    __nv_bfloat16* Bh = (__nv_bfloat16*)pBh;

    cudaFuncSetAttribute(gemm_wmma, cudaFuncAttributeMaxDynamicSharedMemorySize,
                         GEMM_SMEM_MAX);

    const int gemm_grid = NPAD / 128;
    const int aggw_grid = (N_NODES * 32 + 255) / 256;
    const size_t smem2 = (size_t)(1 + 2) * TILE_ELT * 2;   // 104448 B -> 2 CTAs/SM
    const size_t smem1 = (size_t)(1 + 1) * TILE_ELT * 2;   // 69632 B  -> 3 CTAs/SM
    const int csr_grid = (N_EDGES / 4 + 255) / 256;

    // R13 launch layout (proven fastest)
    cudaMemsetAsync(pCnt, 0, N_NODES * sizeof(int));
    count_kernel<<<csr_grid, 256>>>(dst);
    scan_kernel<<<1, 1024>>>();
    wconv_all<<<(5 * 16384 + 255) / 256, 256>>>(Wl0, Wr0, Wl1, Wr1, Wl2, Wr2, Bh);

    // Layer 0 (doesn't need scatter)
    gemm_wmma<<<gemm_grid, 256, smem2>>>(x, nullptr, Bh, 2, Gh, Zh, N_NODES);
    scatter_kernel<<<csr_grid, 256>>>(src, dst);
    agg128_warp<<<aggw_grid, 256>>>(Gh, Zh, bl0, A);

    // Layer 1
    gemm_wmma<<<gemm_grid, 256, smem2>>>(nullptr, A, Bh + 2 * 16384, 2, Gh, Zh, N_NODES);
    agg128_warp<<<aggw_grid, 256>>>(Gh, Zh, bl1, A);

    // Layer 2
    gemm_wmma<<<gemm_grid, 256, smem1>>>(nullptr, A, Bh + 4 * 16384, 1, Gh, Zh, N_NODES);
    agg_lsm47_warp<<<aggw_grid, 256>>>(Gh, Zh, bl2, out);
}